// round 2
// baseline (speedup 1.0000x reference)
#include <cuda_runtime.h>
#include <cstdint>

#define H 1024
#define T 1024
#define NE 16
#define IT 512
#define IV 256

// ---------------- scratch (static __device__, no allocations) ----------------
__device__ float d_G[T * H];            // shared-MLP intermediate  (4 MB)
__device__ float d_act[2 * T * IT];     // per-pair activations     (4 MB), stride IT
__device__ float d_yp[2 * T * H];       // per-pair expert outputs  (8 MB)
__device__ int   d_pairs[2][NE][T];     // token lists per (modality, expert); entry = (token<<1)|slot
__device__ int   d_cnt[2][NE];
__device__ float d_wts[T][2];
__device__ int   d_sel[T][2];
__device__ int   d_modal[T];

// ---------------- helpers ----------------
__device__ __forceinline__ uint32_t f2tf(float f) {
    uint32_t r;
    asm("cvt.rna.tf32.f32 %0, %1;" : "=r"(r) : "f"(f));
    return r;
}

__device__ __forceinline__ void mma_tf32(float* c, const uint32_t* a, uint32_t b0, uint32_t b1) {
    asm volatile(
        "mma.sync.aligned.m16n8k8.row.col.f32.tf32.tf32.f32 "
        "{%0,%1,%2,%3}, {%4,%5,%6,%7}, {%8,%9}, {%0,%1,%2,%3};"
        : "+f"(c[0]), "+f"(c[1]), "+f"(c[2]), "+f"(c[3])
        : "r"(a[0]), "r"(a[1]), "r"(a[2]), "r"(a[3]), "r"(b0), "r"(b1));
}

// ---------------- router: one warp per token ----------------
__global__ __launch_bounds__(256) void k_router(
    const float* __restrict__ x, const int* __restrict__ tt,
    const float* __restrict__ Wt, const float* __restrict__ bt,
    const float* __restrict__ Wv, const float* __restrict__ bv,
    float* __restrict__ logits_out)
{
    int lane = threadIdx.x & 31;
    int t = blockIdx.x * 8 + (threadIdx.x >> 5);
    if (t >= T) return;

    int mod = (tt[t] != 0) ? 1 : 0;
    const float* W = mod ? Wv : Wt;
    const float* bias = mod ? bv : bt;

    float xr[32];
#pragma unroll
    for (int j = 0; j < 32; ++j) xr[j] = x[(size_t)t * H + lane + 32 * j];

    float logit[NE];
#pragma unroll
    for (int e = 0; e < NE; ++e) {
        const float* w = W + (size_t)e * H;
        float s = 0.f;
#pragma unroll
        for (int j = 0; j < 32; ++j) s = fmaf(xr[j], w[lane + 32 * j], s);
#pragma unroll
        for (int o = 16; o; o >>= 1) s += __shfl_xor_sync(0xffffffffu, s, o);
        logit[e] = s;
    }

    // softmax (fp32, accurate exp)
    float mx = logit[0];
#pragma unroll
    for (int e = 1; e < NE; ++e) mx = fmaxf(mx, logit[e]);
    float p[NE], sum = 0.f;
#pragma unroll
    for (int e = 0; e < NE; ++e) { p[e] = expf(logit[e] - mx); sum += p[e]; }
    float inv = 1.f / sum;
#pragma unroll
    for (int e = 0; e < NE; ++e) p[e] *= inv;

    // biased top-2 (first index wins ties, like lax.top_k)
    int i0 = 0; float b0 = -1e30f;
#pragma unroll
    for (int e = 0; e < NE; ++e) { float sc = p[e] + bias[e]; if (sc > b0) { b0 = sc; i0 = e; } }
    int i1 = 0; float b1 = -1e30f;
#pragma unroll
    for (int e = 0; e < NE; ++e) {
        if (e == i0) continue;
        float sc = p[e] + bias[e];
        if (sc > b1) { b1 = sc; i1 = e; }
    }
    float w0 = p[i0], w1 = p[i1];
    float s2 = fmaxf(w0 + w1, 1e-12f);
    w0 /= s2; w1 /= s2;

    if (lane < NE) logits_out[(size_t)t * NE + lane] = logit[lane];
    if (lane == 0) {
        d_sel[t][0] = i0; d_sel[t][1] = i1;
        d_wts[t][0] = w0; d_wts[t][1] = w1;
        d_modal[t] = mod;
    }
}

// ---------------- deterministic list build: warp per (modality, expert) ----------------
__global__ __launch_bounds__(1024) void k_build() {
    int w = threadIdx.x >> 5, lane = threadIdx.x & 31;
    int mod = w >> 4, e = w & 15;
    int cnt = 0;
    for (int base = 0; base < T; base += 32) {
        int t = base + lane;
        int match = 0, slot = 0;
        if (d_modal[t] == mod) {
            if (d_sel[t][0] == e) { match = 1; slot = 0; }
            else if (d_sel[t][1] == e) { match = 1; slot = 1; }
        }
        unsigned m = __ballot_sync(0xffffffffu, match);
        if (match) {
            int pos = cnt + __popc(m & ((1u << lane) - 1u));
            d_pairs[mod][e][pos] = (t << 1) | slot;
        }
        cnt += __popc(m);
    }
    if (lane == 0) d_cnt[mod][e] = cnt;
}

// ---------------- tf32 tiled GEMM core: 64x64 tile, 4 warps, double-buffered ----------------
// GMODE: 0 = direct rows; 1 = A row = pair>>1 (token), C row = pair; 2 = A row = C row = pair
template <int GMODE, bool DUAL, bool SILU>
__device__ __forceinline__ void gemm_core(
    const float* __restrict__ A, int lda,
    const float* __restrict__ B0, const float* __restrict__ B1, int ldb,
    float* __restrict__ C, int ldc,
    int K, int mbase, int nbase,
    const int* __restrict__ plist, int cnt)
{
    __shared__ uint32_t As[2][16][72];
    __shared__ uint32_t Bs0[2][16][72];
    __shared__ uint32_t Bs1[DUAL ? 2 : 1][16][72];
    __shared__ int rowid[64];

    const int tid = threadIdx.x;
    const int lane = tid & 31;
    const int warp = tid >> 5;
    const int wm = warp & 1, wn = warp >> 1;
    const int g = lane >> 2, tg = lane & 3;

    if (GMODE != 0) {
        if (tid < 64) {
            int m = mbase + tid;
            rowid[tid] = (m < cnt) ? plist[m] : -1;
        }
        __syncthreads();
    }

    // A loads: q = tid + 128j -> m = q&63, kq = (q>>6)*4  (coalesced-by-row, conflict-free STS)
    const float* aptr[2];
#pragma unroll
    for (int j = 0; j < 2; ++j) {
        int q = tid + 128 * j;
        int m = q & 63;
        int kq = (q >> 6) * 4;
        int r;
        if (GMODE == 0) r = mbase + m;
        else {
            int pv = rowid[m];
            if (pv < 0) pv = 0;
            r = (GMODE == 1) ? (pv >> 1) : pv;
        }
        aptr[j] = A + (size_t)r * lda + kq;
    }
    // B loads: q -> kb = q>>4, n4 = (q&15)*4 (fully coalesced 256B segments)
    const float* b0ptr[2];
    const float* b1ptr[2];
#pragma unroll
    for (int j = 0; j < 2; ++j) {
        int q = tid + 128 * j;
        int kb = q >> 4;
        int n4 = (q & 15) * 4;
        b0ptr[j] = B0 + (size_t)kb * ldb + nbase + n4;
        b1ptr[j] = DUAL ? (B1 + (size_t)kb * ldb + nbase + n4) : nullptr;
    }

    float acc0[2][4][4];
    float acc1[2][4][4];
#pragma unroll
    for (int a = 0; a < 2; ++a)
#pragma unroll
        for (int b = 0; b < 4; ++b)
#pragma unroll
            for (int c = 0; c < 4; ++c) { acc0[a][b][c] = 0.f; acc1[a][b][c] = 0.f; }

    float4 ar[2], b0r[2], b1r[2];

    auto LDG = [&](int kt) {
        size_t koff = (size_t)kt * 16;
#pragma unroll
        for (int j = 0; j < 2; ++j) {
            ar[j] = *(const float4*)(aptr[j] + koff);
            b0r[j] = *(const float4*)(b0ptr[j] + koff * ldb);
            if (DUAL) b1r[j] = *(const float4*)(b1ptr[j] + koff * ldb);
        }
    };
    auto STS = [&](int buf) {
#pragma unroll
        for (int j = 0; j < 2; ++j) {
            int q = tid + 128 * j;
            int m = q & 63;
            int kq = (q >> 6) * 4;
            As[buf][kq + 0][m] = f2tf(ar[j].x);
            As[buf][kq + 1][m] = f2tf(ar[j].y);
            As[buf][kq + 2][m] = f2tf(ar[j].z);
            As[buf][kq + 3][m] = f2tf(ar[j].w);
            int kb = q >> 4;
            int n4 = (q & 15) * 4;
            uint4 p;
            p.x = f2tf(b0r[j].x); p.y = f2tf(b0r[j].y);
            p.z = f2tf(b0r[j].z); p.w = f2tf(b0r[j].w);
            *(uint4*)&Bs0[buf][kb][n4] = p;
            if (DUAL) {
                uint4 p1;
                p1.x = f2tf(b1r[j].x); p1.y = f2tf(b1r[j].y);
                p1.z = f2tf(b1r[j].z); p1.w = f2tf(b1r[j].w);
                *(uint4*)&Bs1[buf][kb][n4] = p1;
            }
        }
    };
    auto COMPUTE = [&](int buf) {
#pragma unroll
        for (int kk = 0; kk < 2; ++kk) {
            int k0 = kk * 8;
            uint32_t af[2][4];
#pragma unroll
            for (int fm = 0; fm < 2; ++fm) {
                int m0 = wm * 32 + fm * 16 + g;
                af[fm][0] = As[buf][k0 + tg][m0];
                af[fm][1] = As[buf][k0 + tg][m0 + 8];
                af[fm][2] = As[buf][k0 + tg + 4][m0];
                af[fm][3] = As[buf][k0 + tg + 4][m0 + 8];
            }
#pragma unroll
            for (int fn = 0; fn < 4; ++fn) {
                int n0 = wn * 32 + fn * 8 + g;
                uint32_t ba = Bs0[buf][k0 + tg][n0];
                uint32_t bb = Bs0[buf][k0 + tg + 4][n0];
                mma_tf32(acc0[0][fn], af[0], ba, bb);
                mma_tf32(acc0[1][fn], af[1], ba, bb);
                if (DUAL) {
                    uint32_t ca = Bs1[buf][k0 + tg][n0];
                    uint32_t cb = Bs1[buf][k0 + tg + 4][n0];
                    mma_tf32(acc1[0][fn], af[0], ca, cb);
                    mma_tf32(acc1[1][fn], af[1], ca, cb);
                }
            }
        }
    };

    int nk = K >> 4;
    LDG(0);
    STS(0);
    __syncthreads();
    for (int kt = 0; kt < nk; ++kt) {
        int cur = kt & 1;
        if (kt + 1 < nk) LDG(kt + 1);
        COMPUTE(cur);
        if (kt + 1 < nk) STS(cur ^ 1);
        __syncthreads();
    }

    // epilogue
#pragma unroll
    for (int fm = 0; fm < 2; ++fm) {
#pragma unroll
        for (int h = 0; h < 2; ++h) {
            int ml = wm * 32 + fm * 16 + g + h * 8;
            int crow;
            bool valid = true;
            if (GMODE != 0) {
                int pv = rowid[ml];
                valid = (pv >= 0);
                crow = pv;
            } else crow = mbase + ml;
            if (!valid) continue;
#pragma unroll
            for (int fn = 0; fn < 4; ++fn) {
                int nc = nbase + wn * 32 + fn * 8 + 2 * tg;
                float v0, v1;
                if (SILU) {
                    float g0 = acc0[fm][fn][2 * h], g1 = acc0[fm][fn][2 * h + 1];
                    v0 = (g0 / (1.f + __expf(-g0))) * acc1[fm][fn][2 * h];
                    v1 = (g1 / (1.f + __expf(-g1))) * acc1[fm][fn][2 * h + 1];
                } else {
                    v0 = acc0[fm][fn][2 * h];
                    v1 = acc0[fm][fn][2 * h + 1];
                }
                float2 st = make_float2(v0, v1);
                *(float2*)&C[(size_t)crow * ldc + nc] = st;
            }
        }
    }
}

// ---------------- GEMM wrappers ----------------
__global__ __launch_bounds__(128) void k_shared1(
    const float* __restrict__ x, const float* __restrict__ sg, const float* __restrict__ su)
{
    gemm_core<0, true, true>(x, H, sg, su, H, d_G, H, H,
                             blockIdx.x * 64, blockIdx.y * 64, nullptr, 0);
}

__global__ __launch_bounds__(128) void k_shared2(
    const float* __restrict__ sd, float* __restrict__ out)
{
    gemm_core<0, false, false>(d_G, H, sd, nullptr, H, out, H, H,
                               blockIdx.x * 64, blockIdx.y * 64, nullptr, 0);
}

__global__ __launch_bounds__(128) void k_expert_up(
    const float* __restrict__ x, const float* __restrict__ tgu, const float* __restrict__ vgu)
{
    int z = blockIdx.z;
    int mod = z >> 4, e = z & 15;
    int cnt = d_cnt[mod][e];
    int mbase = blockIdx.x * 64;
    if (mbase >= cnt) return;
    int I = mod ? IV : IT;
    int nbase = blockIdx.y * 64;
    if (nbase >= I) return;
    const float* gup = (mod ? vgu : tgu) + (size_t)e * H * 2 * I;
    gemm_core<1, true, true>(x, H, gup, gup + I, 2 * I, d_act, IT, H,
                             mbase, nbase, &d_pairs[mod][e][0], cnt);
}

__global__ __launch_bounds__(128) void k_expert_down(
    const float* __restrict__ tdn, const float* __restrict__ vdn)
{
    int z = blockIdx.z;
    int mod = z >> 4, e = z & 15;
    int cnt = d_cnt[mod][e];
    int mbase = blockIdx.x * 64;
    if (mbase >= cnt) return;
    int I = mod ? IV : IT;
    int nbase = blockIdx.y * 64;
    const float* dn = (mod ? vdn : tdn) + (size_t)e * I * H;
    gemm_core<2, false, false>(d_act, IT, dn, nullptr, H, d_yp, H, I,
                               mbase, nbase, &d_pairs[mod][e][0], cnt);
}

// ---------------- final combine (deterministic, no atomics) ----------------
__global__ __launch_bounds__(256) void k_combine(float* __restrict__ out) {
    int gid = blockIdx.x * blockDim.x + threadIdx.x;   // 0 .. 262143 (float4 units)
    int t = gid >> 8;
    int c4 = gid & 255;
    float w0 = d_wts[t][0], w1 = d_wts[t][1];
    float4 o = ((float4*)out)[gid];
    float4 a = ((const float4*)&d_yp[(size_t)(2 * t) * H])[c4];
    float4 b = ((const float4*)&d_yp[(size_t)(2 * t + 1) * H])[c4];
    o.x += w0 * a.x + w1 * b.x;
    o.y += w0 * a.y + w1 * b.y;
    o.z += w0 * a.z + w1 * b.z;
    o.w += w0 * a.w + w1 * b.w;
    ((float4*)out)[gid] = o;
}

// ---------------- launch ----------------
extern "C" void kernel_launch(void* const* d_in, const int* in_sizes, int n_in,
                              void* d_out, int out_size)
{
    const float* x   = (const float*)d_in[0];
    const int*   tt  = (const int*)d_in[1];
    const float* trw = (const float*)d_in[2];
    const float* tb  = (const float*)d_in[3];
    const float* tgu = (const float*)d_in[4];
    const float* tdn = (const float*)d_in[5];
    const float* vrw = (const float*)d_in[6];
    const float* vb  = (const float*)d_in[7];
    const float* vgu = (const float*)d_in[8];
    const float* vdn = (const float*)d_in[9];
    const float* sg  = (const float*)d_in[10];
    const float* su  = (const float*)d_in[11];
    const float* sd  = (const float*)d_in[12];

    float* out = (float*)d_out;
    float* logits = out + (size_t)T * H;   // [T, NE] after final [1,T,H]

    k_router<<<128, 256>>>(x, tt, trw, tb, vrw, vb, logits);
    k_build<<<1, 1024>>>();
    k_shared1<<<dim3(16, 16), 128>>>(x, sg, su);
    k_shared2<<<dim3(16, 16), 128>>>(sd, out);
    k_expert_up<<<dim3(16, 8, 32), 128>>>(x, tgu, vgu);
    k_expert_down<<<dim3(16, 16, 32), 128>>>(tdn, vdn);
    k_combine<<<1024, 256>>>(out);
}